// round 3
// baseline (speedup 1.0000x reference)
#include <cuda_runtime.h>

#define NN_C   50000
#define DD_C   64
#define EE_C   800000
#define BB_C   50
#define NMAX_C 1000
#define CC_C   100

// ---------------- device scratch (no allocations allowed) ----------------
__device__ float g_xa[NN_C * DD_C];           // x @ W_ma[:64] + b_ma
__device__ float g_agg[NN_C * DD_C];          // segment_sum accumulator
__device__ float g_msgup[BB_C * CC_C * DD_C]; // relu(attr1 @ W_mu + b_mu)
__device__ float g_aggup[NN_C * DD_C];        // nc1 @ msgup (B*NMAX == N rows)

// ---------------- packed fp32x2 helpers ----------------
__device__ __forceinline__ void fma2(unsigned long long& d,
                                     unsigned long long a,
                                     unsigned long long b) {
    asm("fma.rn.f32x2 %0, %1, %2, %0;" : "+l"(d) : "l"(a), "l"(b));
}
__device__ __forceinline__ float2 unpack2(unsigned long long v) {
    float2 f;
    asm("mov.b64 {%0, %1}, %2;" : "=f"(f.x), "=f"(f.y) : "l"(v));
    return f;
}

// ---------------- zero the scatter accumulator ----------------
__global__ __launch_bounds__(256) void zero_kernel(float* __restrict__ p, int n4) {
    float4 z = make_float4(0.f, 0.f, 0.f, 0.f);
    for (int i = blockIdx.x * blockDim.x + threadIdx.x; i < n4;
         i += gridDim.x * blockDim.x)
        ((float4*)p)[i] = z;
}

// ============================================================================
// edge kernel: msg = relu(xa[src] + e@Wb), scatter-add into agg
// k-packed f32x2: acc holds {even-k partial, odd-k partial} per output column.
// 8 edges per warp; W stored as float2 {W[2kp][j], W[2kp+1][j]} in smem.
// ============================================================================
__global__ __launch_bounds__(256) void edge_kernel(
    const float* __restrict__ e, const int* __restrict__ src,
    const int* __restrict__ dst, const float* __restrict__ Wb,
    const float* __restrict__ xa, float* __restrict__ agg, int E)
{
    __shared__ __align__(16) float2 sW2[32 * 64];   // [kpair][j]  16 KB
    __shared__ __align__(16) float4 se[8][8 * 16];  // 8 warps x 8 rows x 16f4 16 KB

    int tid = threadIdx.x;
    for (int i = tid; i < 2048; i += 256) {
        int kp = i >> 6, j = i & 63;
        sW2[i] = make_float2(Wb[(2 * kp) * 64 + j], Wb[(2 * kp + 1) * 64 + j]);
    }
    __syncthreads();

    int warp = tid >> 5, lane = tid & 31;
    int nw = gridDim.x * 8;
    int gw = blockIdx.x * 8 + warp;

    for (int base = gw * 8; base < E; base += nw * 8) {
        int ne = min(8, E - base);
        const float4* ep = (const float4*)(e + (size_t)base * 64);
        int nf4 = ne * 16;
#pragma unroll
        for (int t = 0; t < 4; t++) {
            int idx = lane + 32 * t;
            if (idx < nf4) se[warp][idx] = ep[idx];
        }
        __syncwarp();

        unsigned long long acc0[8], acc1[8];
#pragma unroll
        for (int r = 0; r < 8; r++) { acc0[r] = 0ULL; acc1[r] = 0ULL; }

#pragma unroll 4
        for (int k4 = 0; k4 < 16; k4++) {
            unsigned long long wa0 = *(const unsigned long long*)&sW2[(2 * k4) * 64 + lane];
            unsigned long long wa1 = *(const unsigned long long*)&sW2[(2 * k4) * 64 + lane + 32];
            unsigned long long wb0 = *(const unsigned long long*)&sW2[(2 * k4 + 1) * 64 + lane];
            unsigned long long wb1 = *(const unsigned long long*)&sW2[(2 * k4 + 1) * 64 + lane + 32];
#pragma unroll
            for (int r = 0; r < 8; r++) {
                ulonglong2 ev = *(const ulonglong2*)&se[warp][r * 16 + k4];
                fma2(acc0[r], ev.x, wa0);
                fma2(acc1[r], ev.x, wa1);
                fma2(acc0[r], ev.y, wb0);
                fma2(acc1[r], ev.y, wb1);
            }
        }
#pragma unroll
        for (int r = 0; r < 8; r++) {
            if (r < ne) {
                int s = src[base + r];
                int d = dst[base + r];
                float2 p0 = unpack2(acc0[r]);
                float2 p1 = unpack2(acc1[r]);
                float m0 = fmaxf(p0.x + p0.y + xa[(size_t)s * 64 + lane], 0.f);
                float m1 = fmaxf(p1.x + p1.y + xa[(size_t)s * 64 + lane + 32], 0.f);
                atomicAdd(&agg[(size_t)d * 64 + lane], m0);
                atomicAdd(&agg[(size_t)d * 64 + lane + 32], m1);
            }
        }
        __syncwarp();
    }
}

// ============================================================================
// generic [R,64] @ [64,64] + bias (opt relu), k-packed f32x2, 8 rows/warp
// ============================================================================
template <bool RELU>
__global__ __launch_bounds__(256) void rowmm2_kernel(
    const float* __restrict__ in, const float* __restrict__ W,
    const float* __restrict__ bias, float* __restrict__ outp, int R)
{
    __shared__ __align__(16) float2 sW2[32 * 64];
    __shared__ float sb[64];
    __shared__ __align__(16) float4 srow[8][8 * 16];

    int tid = threadIdx.x;
    for (int i = tid; i < 2048; i += 256) {
        int kp = i >> 6, j = i & 63;
        sW2[i] = make_float2(W[(2 * kp) * 64 + j], W[(2 * kp + 1) * 64 + j]);
    }
    if (tid < 64) sb[tid] = bias[tid];
    __syncthreads();

    int warp = tid >> 5, lane = tid & 31;
    int nw = gridDim.x * 8;
    int gw = blockIdx.x * 8 + warp;

    for (int base = gw * 8; base < R; base += nw * 8) {
        int nr = min(8, R - base);
        const float4* ip = (const float4*)(in + (size_t)base * 64);
        int nf4 = nr * 16;
#pragma unroll
        for (int t = 0; t < 4; t++) {
            int idx = lane + 32 * t;
            if (idx < nf4) srow[warp][idx] = ip[idx];
        }
        __syncwarp();

        unsigned long long acc0[8], acc1[8];
#pragma unroll
        for (int r = 0; r < 8; r++) { acc0[r] = 0ULL; acc1[r] = 0ULL; }

#pragma unroll 4
        for (int k4 = 0; k4 < 16; k4++) {
            unsigned long long wa0 = *(const unsigned long long*)&sW2[(2 * k4) * 64 + lane];
            unsigned long long wa1 = *(const unsigned long long*)&sW2[(2 * k4) * 64 + lane + 32];
            unsigned long long wb0 = *(const unsigned long long*)&sW2[(2 * k4 + 1) * 64 + lane];
            unsigned long long wb1 = *(const unsigned long long*)&sW2[(2 * k4 + 1) * 64 + lane + 32];
#pragma unroll
            for (int r = 0; r < 8; r++) {
                ulonglong2 ev = *(const ulonglong2*)&srow[warp][r * 16 + k4];
                fma2(acc0[r], ev.x, wa0);
                fma2(acc1[r], ev.x, wa1);
                fma2(acc0[r], ev.y, wb0);
                fma2(acc1[r], ev.y, wb1);
            }
        }
#pragma unroll
        for (int r = 0; r < 8; r++) {
            if (r < nr) {
                float2 p0 = unpack2(acc0[r]);
                float2 p1 = unpack2(acc1[r]);
                float o0 = p0.x + p0.y + sb[lane];
                float o1 = p1.x + p1.y + sb[lane + 32];
                if (RELU) { o0 = fmaxf(o0, 0.f); o1 = fmaxf(o1, 0.f); }
                outp[(size_t)(base + r) * 64 + lane]      = o0;
                outp[(size_t)(base + r) * 64 + lane + 32] = o1;
            }
        }
        __syncwarp();
    }
}

// ============================================================================
// pooling: agg_up[b] = nc1[b] @ msgup[b]   ([1000,100] @ [100,64] per batch)
// k-packed f32x2, 4 rows per warp (smem budget), K=100 -> 25 k4 iters
// ============================================================================
__global__ __launch_bounds__(256) void aggup2_kernel(
    const float* __restrict__ nc1, const float* __restrict__ msgup,
    float* __restrict__ outp)
{
    __shared__ __align__(16) float2 sM2[50 * 64];     // 25.6 KB
    __shared__ __align__(16) float4 sn[8][4 * 26];    // 4 rows x 104 floats

    int b = blockIdx.x;
    int tid = threadIdx.x;
    const float* mp = msgup + (size_t)b * CC_C * 64;
    for (int i = tid; i < 50 * 64; i += 256) {
        int kp = i >> 6, j = i & 63;
        sM2[i] = make_float2(mp[(2 * kp) * 64 + j], mp[(2 * kp + 1) * 64 + j]);
    }
    __syncthreads();

    int warp = tid >> 5, lane = tid & 31;
    int n0 = blockIdx.y * 32 + warp * 4;
    if (n0 >= NMAX_C) return;
    int ne = min(4, NMAX_C - n0);

    const float4* srcp = (const float4*)(nc1 + ((size_t)b * NMAX_C + n0) * CC_C);
    // 4 rows x 25 float4 = 100 float4; row stride in smem = 26 float4 (pad)
#pragma unroll
    for (int t = 0; t < 4; t++) {
        int idx = lane + 32 * t;
        if (idx < ne * 25) {
            int r = idx / 25, c = idx - r * 25;
            sn[warp][r * 26 + c] = srcp[idx];
        }
    }
    __syncwarp();

    unsigned long long acc0[4], acc1[4];
#pragma unroll
    for (int r = 0; r < 4; r++) { acc0[r] = 0ULL; acc1[r] = 0ULL; }

#pragma unroll 5
    for (int k4 = 0; k4 < 25; k4++) {
        unsigned long long wa0 = *(const unsigned long long*)&sM2[(2 * k4) * 64 + lane];
        unsigned long long wa1 = *(const unsigned long long*)&sM2[(2 * k4) * 64 + lane + 32];
        unsigned long long wb0 = *(const unsigned long long*)&sM2[(2 * k4 + 1) * 64 + lane];
        unsigned long long wb1 = *(const unsigned long long*)&sM2[(2 * k4 + 1) * 64 + lane + 32];
#pragma unroll
        for (int r = 0; r < 4; r++) {
            ulonglong2 ev = *(const ulonglong2*)&sn[warp][r * 26 + k4];
            fma2(acc0[r], ev.x, wa0);
            fma2(acc1[r], ev.x, wa1);
            fma2(acc0[r], ev.y, wb0);
            fma2(acc1[r], ev.y, wb1);
        }
    }
#pragma unroll
    for (int r = 0; r < 4; r++) {
        if (r < ne) {
            float2 p0 = unpack2(acc0[r]);
            float2 p1 = unpack2(acc1[r]);
            size_t o = ((size_t)b * NMAX_C + n0 + r) * 64;
            outp[o + lane]      = p0.x + p0.y;
            outp[o + lane + 32] = p1.x + p1.y;
        }
    }
}

// ============================================================================
// fused node kernel:
//   h1 = agg + (1+e1)x ; h2 = aggup[xidx] + (1+e2)x
//   v  = [relu(h1@Wua+bua), relu(h2@Wuu+buu)]   (kept in smem)
//   out = v @ Wc + bc
// dynamic smem: Wa pairs 16K | Wu pairs 16K | Wc pairs 32K | biases | staging
// ============================================================================
__global__ __launch_bounds__(256) void node_kernel(
    const float* __restrict__ x, const float* __restrict__ agg,
    const float* __restrict__ aggup, const int* __restrict__ xidx,
    const float* __restrict__ eps1, const float* __restrict__ eps2,
    const float* __restrict__ Wua, const float* __restrict__ bua,
    const float* __restrict__ Wuu, const float* __restrict__ buu,
    const float* __restrict__ Wc, const float* __restrict__ bc,
    float* __restrict__ outp, int Nn)
{
    extern __shared__ __align__(16) char dyn[];
    float2* sWa = (float2*)dyn;            // 2048 float2
    float2* sWu = sWa + 2048;              // 2048 float2
    float2* sWc = sWu + 2048;              // 4096 float2
    float*  sB  = (float*)(sWc + 4096);    // 192 floats: bua|buu|bc
    float*  sh  = sB + 192;                // 8 warps * 8 rows * 132 floats

    int tid = threadIdx.x;
    for (int i = tid; i < 2048; i += 256) {
        int kp = i >> 6, j = i & 63;
        sWa[i] = make_float2(Wua[(2 * kp) * 64 + j], Wua[(2 * kp + 1) * 64 + j]);
        sWu[i] = make_float2(Wuu[(2 * kp) * 64 + j], Wuu[(2 * kp + 1) * 64 + j]);
    }
    for (int i = tid; i < 4096; i += 256) {
        int kp = i >> 6, j = i & 63;
        sWc[i] = make_float2(Wc[(2 * kp) * 64 + j], Wc[(2 * kp + 1) * 64 + j]);
    }
    if (tid < 64) {
        sB[tid]       = bua[tid];
        sB[64 + tid]  = buu[tid];
        sB[128 + tid] = bc[tid];
    }
    __syncthreads();

    float c1 = 1.f + eps1[0];
    float c2 = 1.f + eps2[0];
    int warp = tid >> 5, lane = tid & 31;
    int nw = gridDim.x * 8;
    int gw = blockIdx.x * 8 + warp;
    float* mh = sh + warp * 8 * 132;

    for (int base = gw * 8; base < Nn; base += nw * 8) {
        int nr = min(8, Nn - base);
        // ---- build h1|h2 rows in smem (each lane writes 4 values/row) ----
#pragma unroll
        for (int r = 0; r < 8; r++) {
            if (r < nr) {
                int n = base + r;
                int up = xidx[n];
                float x0 = x[(size_t)n * 64 + lane];
                float x1 = x[(size_t)n * 64 + lane + 32];
                mh[r * 132 + lane]       = agg[(size_t)n * 64 + lane]        + c1 * x0;
                mh[r * 132 + lane + 32]  = agg[(size_t)n * 64 + lane + 32]   + c1 * x1;
                mh[r * 132 + 64 + lane]      = aggup[(size_t)up * 64 + lane]      + c2 * x0;
                mh[r * 132 + 64 + lane + 32] = aggup[(size_t)up * 64 + lane + 32] + c2 * x1;
            }
        }
        __syncwarp();

        // ---- GEMM1: v1 = relu(h1 @ Wua + bua) ----
        unsigned long long acc0[8], acc1[8];
#pragma unroll
        for (int r = 0; r < 8; r++) { acc0[r] = 0ULL; acc1[r] = 0ULL; }
#pragma unroll 4
        for (int k4 = 0; k4 < 16; k4++) {
            unsigned long long wa0 = *(const unsigned long long*)&sWa[(2 * k4) * 64 + lane];
            unsigned long long wa1 = *(const unsigned long long*)&sWa[(2 * k4) * 64 + lane + 32];
            unsigned long long wb0 = *(const unsigned long long*)&sWa[(2 * k4 + 1) * 64 + lane];
            unsigned long long wb1 = *(const unsigned long long*)&sWa[(2 * k4 + 1) * 64 + lane + 32];
#pragma unroll
            for (int r = 0; r < 8; r++) {
                ulonglong2 ev = *(const ulonglong2*)&mh[r * 132 + 4 * k4];
                fma2(acc0[r], ev.x, wa0);
                fma2(acc1[r], ev.x, wa1);
                fma2(acc0[r], ev.y, wb0);
                fma2(acc1[r], ev.y, wb1);
            }
        }
        float v1a[8], v1b[8];
#pragma unroll
        for (int r = 0; r < 8; r++) {
            float2 p0 = unpack2(acc0[r]);
            float2 p1 = unpack2(acc1[r]);
            v1a[r] = fmaxf(p0.x + p0.y + sB[lane], 0.f);
            v1b[r] = fmaxf(p1.x + p1.y + sB[lane + 32], 0.f);
        }

        // ---- GEMM2: v2 = relu(h2 @ Wuu + buu) ----
#pragma unroll
        for (int r = 0; r < 8; r++) { acc0[r] = 0ULL; acc1[r] = 0ULL; }
#pragma unroll 4
        for (int k4 = 0; k4 < 16; k4++) {
            unsigned long long wa0 = *(const unsigned long long*)&sWu[(2 * k4) * 64 + lane];
            unsigned long long wa1 = *(const unsigned long long*)&sWu[(2 * k4) * 64 + lane + 32];
            unsigned long long wb0 = *(const unsigned long long*)&sWu[(2 * k4 + 1) * 64 + lane];
            unsigned long long wb1 = *(const unsigned long long*)&sWu[(2 * k4 + 1) * 64 + lane + 32];
#pragma unroll
            for (int r = 0; r < 8; r++) {
                ulonglong2 ev = *(const ulonglong2*)&mh[r * 132 + 64 + 4 * k4];
                fma2(acc0[r], ev.x, wa0);
                fma2(acc1[r], ev.x, wa1);
                fma2(acc0[r], ev.y, wb0);
                fma2(acc1[r], ev.y, wb1);
            }
        }
        __syncwarp();   // all h reads done before overwriting with v
#pragma unroll
        for (int r = 0; r < 8; r++) {
            float2 p0 = unpack2(acc0[r]);
            float2 p1 = unpack2(acc1[r]);
            mh[r * 132 + lane]      = v1a[r];
            mh[r * 132 + lane + 32] = v1b[r];
            mh[r * 132 + 64 + lane]      = fmaxf(p0.x + p0.y + sB[64 + lane], 0.f);
            mh[r * 132 + 64 + lane + 32] = fmaxf(p1.x + p1.y + sB[64 + lane + 32], 0.f);
        }
        __syncwarp();

        // ---- GEMM3: out = v @ Wc + bc   (K = 128) ----
#pragma unroll
        for (int r = 0; r < 8; r++) { acc0[r] = 0ULL; acc1[r] = 0ULL; }
#pragma unroll 4
        for (int k4 = 0; k4 < 32; k4++) {
            unsigned long long wa0 = *(const unsigned long long*)&sWc[(2 * k4) * 64 + lane];
            unsigned long long wa1 = *(const unsigned long long*)&sWc[(2 * k4) * 64 + lane + 32];
            unsigned long long wb0 = *(const unsigned long long*)&sWc[(2 * k4 + 1) * 64 + lane];
            unsigned long long wb1 = *(const unsigned long long*)&sWc[(2 * k4 + 1) * 64 + lane + 32];
#pragma unroll
            for (int r = 0; r < 8; r++) {
                ulonglong2 ev = *(const ulonglong2*)&mh[r * 132 + 4 * k4];
                fma2(acc0[r], ev.x, wa0);
                fma2(acc1[r], ev.x, wa1);
                fma2(acc0[r], ev.y, wb0);
                fma2(acc1[r], ev.y, wb1);
            }
        }
#pragma unroll
        for (int r = 0; r < 8; r++) {
            if (r < nr) {
                float2 p0 = unpack2(acc0[r]);
                float2 p1 = unpack2(acc1[r]);
                outp[(size_t)(base + r) * 64 + lane]      = p0.x + p0.y + sB[128 + lane];
                outp[(size_t)(base + r) * 64 + lane + 32] = p1.x + p1.y + sB[128 + lane + 32];
            }
        }
        __syncwarp();
    }
}

// ---------------- launch ----------------
extern "C" void kernel_launch(void* const* d_in, const int* in_sizes, int n_in,
                              void* d_out, int out_size)
{
    const float* x     = (const float*)d_in[0];
    const float* e     = (const float*)d_in[1];
    const int*   ei    = (const int*)d_in[2];
    const float* attr1 = (const float*)d_in[3];
    const float* nc1   = (const float*)d_in[4];
    const int*   xidx  = (const int*)d_in[5];
    const float* eps1  = (const float*)d_in[6];
    const float* eps2  = (const float*)d_in[7];
    const float* Wma   = (const float*)d_in[8];
    const float* bma   = (const float*)d_in[9];
    const float* Wmu   = (const float*)d_in[10];
    const float* bmu   = (const float*)d_in[11];
    const float* Wua   = (const float*)d_in[12];
    const float* bua   = (const float*)d_in[13];
    const float* Wuu   = (const float*)d_in[14];
    const float* buu   = (const float*)d_in[15];
    const float* Wc    = (const float*)d_in[16];
    const float* bc    = (const float*)d_in[17];
    float* out = (float*)d_out;

    int N = in_sizes[0] / 64;
    int E = in_sizes[2] / 2;

    float *p_xa, *p_agg, *p_msgup, *p_aggup;
    cudaGetSymbolAddress((void**)&p_xa,    g_xa);
    cudaGetSymbolAddress((void**)&p_agg,   g_agg);
    cudaGetSymbolAddress((void**)&p_msgup, g_msgup);
    cudaGetSymbolAddress((void**)&p_aggup, g_aggup);

    static int node_smem_set = 0;
    const int NODE_SMEM = (2048 + 2048 + 4096) * 8 + 192 * 4 + 8 * 8 * 132 * 4;
    if (!node_smem_set) {
        cudaFuncSetAttribute(node_kernel,
                             cudaFuncAttributeMaxDynamicSharedMemorySize, NODE_SMEM);
        node_smem_set = 1;
    }

    // 1) zero the scatter accumulator
    zero_kernel<<<512, 256>>>(p_agg, N * 64 / 4);

    // 2) xa = x @ W_ma[:64] + b_ma
    rowmm2_kernel<false><<<(N + 63) / 64, 256>>>(x, Wma, bma, p_xa, N);

    // 3) msg_up = relu(attr1 @ W_mu + b_mu)
    rowmm2_kernel<true><<<(BB_C * CC_C + 63) / 64, 256>>>(attr1, Wmu, bmu,
                                                          p_msgup, BB_C * CC_C);

    // 4) edge MLP + scatter-sum (dominant)
    edge_kernel<<<1184, 256>>>(e, ei, ei + E, Wma + 64 * 64, p_xa, p_agg, E);

    // 5) agg_up[b] = nc1[b] @ msg_up[b]
    aggup2_kernel<<<dim3(BB_C, (NMAX_C + 31) / 32), 256>>>(nc1, p_msgup, p_aggup);

    // 6+7) fused: v = [relu(h1@Wua+b), relu(h2@Wuu+b)]; out = v @ Wc + bc
    node_kernel<<<(N + 63) / 64, 256, NODE_SMEM>>>(
        x, p_agg, p_aggup, xidx, eps1, eps2,
        Wua, bua, Wuu, buu, Wc, bc, out, N);
}